// round 14
// baseline (speedup 1.0000x reference)
#include <cuda_runtime.h>
#include <cuda_fp16.h>
#include <math.h>
#include <stdint.h>

// ---------------- problem constants ----------------
#define B_      128
#define STREAM_ 512
#define INCH    4
#define EXTRA_  5
#define G_      2
#define STEP_   16
#define SIGC    1110        // C + C^2 + C^3, C=10
#define W_      31          // windows
#define F_      2220        // GROUPS * SIGC
#define RNN_    256
#define OUT_    10
#define KP2     2240        // F_ padded to multiple of 64 (fp16 chunk)
#define MROWS   (W_ * B_)   // 3968
#define NGI     768         // 3 * RNN
#define NC      (KP2 / 64)  // 35 K-chunks of 64 fp16 (128 bytes)

// ---------------- device scratch (static, allowed) ----------------
__device__ __half g_A0[MROWS * KP2];          // sig fp16 (~17.8 MB)
__device__ __half g_B0[NGI * KP2];            // W_ih fp16 (~3.4 MB)
__device__ float g_gi[MROWS * NGI];           // [t][b][gate] (~12 MB)
__device__ float g_h [2][B_ * RNN_];          // ping-pong hidden state

// per-bt flag barrier: 16 words used per bt group, padded to 128B line
__device__ unsigned g_flags[8][32];

// ---------------- PTX helpers (portable: sm_80/90 class only) ----------------
__device__ __forceinline__ uint32_t smem_u32(const void* p) {
    uint32_t a;
    asm("{ .reg .u64 t; cvta.to.shared.u64 t, %1; cvt.u32.u64 %0, t; }" : "=r"(a) : "l"(p));
    return a;
}

__device__ __forceinline__ uint32_t swz(uint32_t off) { return off ^ ((off >> 3) & 0x70); }

#define LDSM4(r0, r1, r2, r3, addr)                                               \
    asm volatile("ldmatrix.sync.aligned.m8n8.x4.shared.b16 {%0,%1,%2,%3}, [%4];"  \
        : "=r"(r0), "=r"(r1), "=r"(r2), "=r"(r3) : "r"(addr))

// D += A(16x16) * B(16x8), fp16 in, fp32 accum. row.col = both K-contiguous.
#define MMAH(d, a, b0v, b1v)                                                      \
    asm volatile("mma.sync.aligned.m16n8k16.row.col.f32.f16.f16.f32 "             \
        "{%0,%1,%2,%3}, {%4,%5,%6,%7}, {%8,%9}, {%0,%1,%2,%3};"                   \
        : "+f"((d)[0]), "+f"((d)[1]), "+f"((d)[2]), "+f"((d)[3])                  \
        : "r"((a)[0]), "r"((a)[1]), "r"((a)[2]), "r"((a)[3]), "r"(b0v), "r"(b1v))

__device__ __forceinline__ uint32_t pack_h2(float a, float b) {
    __half2 h = __halves2half2(__float2half_rn(a), __float2half_rn(b));
    return *(uint32_t*)&h;
}

// =====================================================================
// Kernel 1: path signatures (Chen, depth 3) -> fp16 (single-rounded)
// =====================================================================
__global__ __launch_bounds__(128) void sig_kernel(
    const float* __restrict__ x,       // (128,512,4)
    const float* __restrict__ W_aug)   // (2,5,4)
{
    const int w  = blockIdx.x;
    const int bg = blockIdx.y;
    const int b  = bg >> 1;
    const int g  = bg & 1;
    const int tid = threadIdx.x;

    __shared__ __align__(16) float xs[32][4];
    __shared__ __align__(16) float dxw[31][10];

    {
        int row = tid >> 2, ch = tid & 3;
        xs[row][ch] = x[(b * STREAM_ + w * STEP_ + row) * INCH + ch];
    }
    __syncthreads();

    for (int idx = tid; idx < 31 * 10; idx += 128) {
        int j = idx / 10, c = idx % 10;
        float v;
        if (c < 4) {
            v = xs[j + 1][c] - xs[j][c];
        } else if (c == 4) {
            v = 1.0f / 511.0f;
        } else {
            int e = c - 5;
            const float* wa = W_aug + (g * EXTRA_ + e) * INCH;
            v = 0.f;
            #pragma unroll
            for (int i = 0; i < 4; i++) v += wa[i] * (xs[j + 1][i] - xs[j][i]);
        }
        dxw[j][c] = v;
    }
    __syncthreads();

    const size_t base = (size_t)(w * B_ + b) * KP2 + (size_t)g * SIGC;

    if (tid < 100) {
        const int a  = tid / 10;
        const int bb = tid % 10;
        float s1a = 0.f, s2 = 0.f;
        float s3[10];
        #pragma unroll
        for (int c = 0; c < 10; c++) s3[c] = 0.f;

        for (int j = 0; j < 31; j++) {
            float dxa = dxw[j][a];
            float dxb = dxw[j][bb];
            float factor = s2 + dxb * (0.5f * s1a + (1.0f / 6.0f) * dxa);
            #pragma unroll
            for (int c = 0; c < 10; c++) s3[c] += factor * dxw[j][c];
            s2  += dxb * (s1a + 0.5f * dxa);
            s1a += dxa;
        }
        if (bb == 0) g_A0[base + a] = __float2half_rn(s1a);
        g_A0[base + 10 + tid] = __float2half_rn(s2);
        #pragma unroll
        for (int c = 0; c < 10; c++)
            g_A0[base + 110 + tid * 10 + c] = __float2half_rn(s3[c]);
    }
    // zero K-pad columns (g==1 block handles it once per row)
    if (g == 1 && tid < (KP2 - F_))
        g_A0[(size_t)(w * B_ + b) * KP2 + F_ + tid] = __float2half_rn(0.f);
}

// =====================================================================
// Kernel 2: round+pad W_ih (768 x 2220) into g_B0 (768 x 2240) fp16
// =====================================================================
__global__ __launch_bounds__(256) void prep_w(const float* __restrict__ Wih)
{
    int idx = blockIdx.x * 256 + threadIdx.x;
    if (idx < NGI * KP2) {
        int n = idx / KP2, k = idx - n * KP2;
        float v = (k < F_) ? Wih[n * F_ + k] : 0.f;
        g_B0[idx] = __float2half_rn(v);
    }
}

// =====================================================================
// Kernel 3: GI = sig @ W_ih^T + b_ih, SINGLE-product fp16 mma.sync.
// 64x128 CTA tile (372 CTAs, 2/SM), 8 warps of 32(M)x32(N).
// =====================================================================
#define A_TILE_B    8192                   // 64 rows x 128 bytes
#define B_TILE_B    16384                  // 128 rows x 128 bytes
#define STAGE_B     (A_TILE_B + B_TILE_B)  // 24576
#define GEMM_SMEM   (2 * STAGE_B)          // 49152 bytes (2 stages)

__global__ __launch_bounds__(256, 2) void gemm_mma(const float* __restrict__ bih)
{
    extern __shared__ char smem[];
    const uint32_t sb = smem_u32(smem);
    const int tid  = threadIdx.x;
    const int lane = tid & 31;
    const int wid  = tid >> 5;
    const int wm   = wid & 1;         // M offset 32*wm
    const int wn   = wid >> 1;        // 0..3 -> N offset 32*wn
    const int m0 = blockIdx.x * 64;
    const int n0 = blockIdx.y * 128;

    const __half* aA0  = g_A0 + (size_t)m0 * KP2;
    const __half* bB0g = g_B0 + (size_t)n0 * KP2;

    auto load_chunk = [&](int c) {
        uint32_t sbase = sb + (uint32_t)(c & 1) * STAGE_B;
        #pragma unroll
        for (int it = 0; it < 2; it++) {
            int i = tid + it * 256;               // 0..511
            int row = i >> 3, seg = i & 7;
            uint32_t dst = sbase + swz((uint32_t)row * 128 + (uint32_t)seg * 16);
            const void* src = aA0 + (size_t)row * KP2 + (size_t)c * 64 + seg * 8;
            asm volatile("cp.async.cg.shared.global [%0], [%1], 16;\n"
                         :: "r"(dst), "l"(src));
        }
        #pragma unroll
        for (int it = 0; it < 4; it++) {
            int i = tid + it * 256;               // 0..1023
            int row = i >> 3, seg = i & 7;
            uint32_t dst = sbase + A_TILE_B
                         + swz((uint32_t)row * 128 + (uint32_t)seg * 16);
            const void* src = bB0g + (size_t)row * KP2 + (size_t)c * 64 + seg * 8;
            asm volatile("cp.async.cg.shared.global [%0], [%1], 16;\n"
                         :: "r"(dst), "l"(src));
        }
        asm volatile("cp.async.commit_group;\n" ::: "memory");
    };

    float acc[2][4][4];
    #pragma unroll
    for (int i = 0; i < 2; i++)
        #pragma unroll
        for (int jj = 0; jj < 4; jj++)
            #pragma unroll
            for (int k = 0; k < 4; k++) acc[i][jj][k] = 0.f;

    const uint32_t a_row  = (uint32_t)(wm * 32 + (lane & 15));
    const uint32_t a_byte = (uint32_t)((lane >> 4) << 4);
    const uint32_t b_row  = (uint32_t)(wn * 32 + (lane & 7) + ((lane >> 4) << 3));
    const uint32_t b_byte = (uint32_t)((lane & 8) << 1);

    load_chunk(0);

    for (int c = 0; c < NC; c++) {
        if (c + 1 < NC) load_chunk(c + 1);
        if (c + 1 < NC) asm volatile("cp.async.wait_group 1;\n" ::: "memory");
        else            asm volatile("cp.async.wait_group 0;\n" ::: "memory");
        __syncthreads();

        const uint32_t stage = sb + (uint32_t)(c & 1) * STAGE_B;
        const uint32_t aB0 = stage;
        const uint32_t bB0 = stage + A_TILE_B;

        #pragma unroll
        for (int ks = 0; ks < 4; ks++) {
            const uint32_t kb = (uint32_t)ks * 32;
            uint32_t a0f[2][4];
            #pragma unroll
            for (int mt = 0; mt < 2; mt++) {
                uint32_t off = swz((a_row + mt * 16) * 128 + kb + a_byte);
                LDSM4(a0f[mt][0], a0f[mt][1], a0f[mt][2], a0f[mt][3], aB0 + off);
            }
            uint32_t b0f[2][4];
            #pragma unroll
            for (int nt = 0; nt < 2; nt++) {
                uint32_t off = swz((b_row + nt * 16) * 128 + kb + b_byte);
                LDSM4(b0f[nt][0], b0f[nt][1], b0f[nt][2], b0f[nt][3], bB0 + off);
            }
            #pragma unroll
            for (int mt = 0; mt < 2; mt++) {
                #pragma unroll
                for (int nt = 0; nt < 2; nt++) {
                    MMAH(acc[mt][2 * nt],     a0f[mt], b0f[nt][0], b0f[nt][1]);
                    MMAH(acc[mt][2 * nt + 1], a0f[mt], b0f[nt][2], b0f[nt][3]);
                }
            }
        }
        __syncthreads();
    }

    float2 bias[4];
    {
        const int nbase = n0 + wn * 32 + 2 * (lane & 3);
        #pragma unroll
        for (int nt8 = 0; nt8 < 4; nt8++) {
            bias[nt8].x = bih[nbase + nt8 * 8];
            bias[nt8].y = bih[nbase + nt8 * 8 + 1];
        }
    }
    #pragma unroll
    for (int mt = 0; mt < 2; mt++) {
        const int mlo = m0 + wm * 32 + mt * 16 + (lane >> 2);
        #pragma unroll
        for (int nt8 = 0; nt8 < 4; nt8++) {
            const int n = n0 + wn * 32 + nt8 * 8 + 2 * (lane & 3);
            float2 lo, hi;
            lo.x = acc[mt][nt8][0] + bias[nt8].x;
            lo.y = acc[mt][nt8][1] + bias[nt8].y;
            hi.x = acc[mt][nt8][2] + bias[nt8].x;
            hi.y = acc[mt][nt8][3] + bias[nt8].y;
            *(float2*)(g_gi + (size_t)mlo * NGI + n)       = lo;
            *(float2*)(g_gi + (size_t)(mlo + 8) * NGI + n) = hi;
        }
    }
}

// =====================================================================
// Kernel 4: persistent GRU v5 — MMA gh (R13) + per-bt 16-CTA FLAG
// barrier (no atomics, no release wave). 128 CTAs = 8 bt x 16 jt.
// Arrival: own-word store (monotonic base+t+1, replay-safe); depart:
// lanes 0..15 spin on the 16 words of this bt's 64B flag sector.
// =====================================================================
#define GRU_CTAS   128
#define HROWH      264      // 256 + 8 halves pad (conflict-free LDSM)

__global__ __launch_bounds__(256, 1) void gru_persist(
    const float* __restrict__ Whh,   // (768,256)
    const float* __restrict__ bhh,   // (768)
    const float* __restrict__ Wout,  // (10,256)
    const float* __restrict__ bout,  // (10)
    float* __restrict__ out)         // (128,10)
{
    __shared__ __align__(16) __half hs0[16][HROWH];   // 8.25 KB
    __shared__ __align__(16) __half hs1[16][HROWH];
    __shared__ __align__(16) float  ghs[16][66];      // 4.1 KB

    const int tid  = threadIdx.x;
    const int w    = tid >> 5;
    const int lane = tid & 31;
    const int bt = blockIdx.x >> 4, jt = blockIdx.x & 15;
    const int b0 = bt * 16, j0 = jt * 16;

    // this thread's gate-output assignment (independent of warp role)
    const int obb = tid >> 4, ojl = tid & 15;
    const int ob  = b0 + obb, oj = j0 + ojl;
    const float br = bhh[oj], bz = bhh[RNN_ + oj], bn = bhh[2 * RNN_ + oj];

    // flag-barrier base (monotonic across graph replays; all flags equal
    // at every launch boundary by induction from zero-init)
    const unsigned fbase = *(volatile unsigned*)&g_flags[bt][jt];

    // ---- one-time: W_hh B-fragments (W0 + residual W1) in registers ----
    const bool active = (w < 6);
    uint32_t WF0[16][2], WF1[16][2];
    if (active) {
        const int colg = 8 * w + (lane >> 2);            // 0..47
        const int jrow = (colg >> 4) * RNN_ + j0 + (colg & 15);
        const float* wr = Whh + (size_t)jrow * RNN_;
        const int k2 = (lane & 3) * 2;
        #pragma unroll
        for (int ks = 0; ks < 16; ks++) {
            const int kb = ks * 16 + k2;
            float v0 = wr[kb], v1 = wr[kb + 1], v8 = wr[kb + 8], v9 = wr[kb + 9];
            __half h0 = __float2half_rn(v0), h1 = __float2half_rn(v1);
            __half h8 = __float2half_rn(v8), h9 = __float2half_rn(v9);
            WF0[ks][0] = pack_h2(v0, v1);
            WF0[ks][1] = pack_h2(v8, v9);
            WF1[ks][0] = pack_h2(v0 - __half2float(h0), v1 - __half2float(h1));
            WF1[ks][1] = pack_h2(v8 - __half2float(h8), v9 - __half2float(h9));
        }
    }

    // prefetch gi for t=0
    float ir, iz, inn;
    {
        const float* gi0 = g_gi + (size_t)ob * NGI;
        ir  = __ldcg(&gi0[oj]);
        iz  = __ldcg(&gi0[RNN_ + oj]);
        inn = __ldcg(&gi0[2 * RNN_ + oj]);
    }

    const uint32_t hb0 = smem_u32(&hs0[0][0]);
    const uint32_t hb1 = smem_u32(&hs1[0][0]);
    const uint32_t aoff_base = (uint32_t)(lane & 15) * (HROWH * 2)
                             + (uint32_t)((lane >> 4) << 4);

    for (int t = 0; t < W_; t++) {
        // ---- fill hs0/hs1 with exact fp16 split of h_t (zeros at t=0) ----
        if (t == 0) {
            for (int i = tid; i < 16 * HROWH / 2; i += 256) {
                ((uint32_t*)hs0)[i] = 0u;
                ((uint32_t*)hs1)[i] = 0u;
            }
        } else {
            const float* hi = g_h[t & 1];
            const int row = tid >> 4, cb = (tid & 15) * 16;
            const float* src = &hi[(b0 + row) * RNN_ + cb];
            float v[16];
            #pragma unroll
            for (int q = 0; q < 4; q++)
                *(float4*)&v[q * 4] = __ldcg((const float4*)&src[q * 4]);
            uint32_t p0[8], p1[8];
            #pragma unroll
            for (int e = 0; e < 8; e++) {
                float a = v[2 * e], bvl = v[2 * e + 1];
                __half ha = __float2half_rn(a), hbv = __float2half_rn(bvl);
                p0[e] = pack_h2(a, bvl);
                p1[e] = pack_h2(a - __half2float(ha), bvl - __half2float(hbv));
            }
            uint32_t* d0 = (uint32_t*)&hs0[row][cb];
            uint32_t* d1 = (uint32_t*)&hs1[row][cb];
            *(uint4*)&d0[0] = *(uint4*)&p0[0];
            *(uint4*)&d0[4] = *(uint4*)&p0[4];
            *(uint4*)&d1[0] = *(uint4*)&p1[0];
            *(uint4*)&d1[4] = *(uint4*)&p1[4];
        }
        __syncthreads();

        // ---- MMA: gh[16][8] per active warp, K=256 ----
        if (active) {
            float C[4] = {0.f, 0.f, 0.f, 0.f};
            #pragma unroll
            for (int ks = 0; ks < 16; ks++) {
                const uint32_t off = aoff_base + (uint32_t)ks * 32;
                uint32_t A0[4], A1[4];
                LDSM4(A0[0], A0[1], A0[2], A0[3], hb0 + off);
                LDSM4(A1[0], A1[1], A1[2], A1[3], hb1 + off);
                MMAH(C, A0, WF0[ks][0], WF0[ks][1]);
                MMAH(C, A0, WF1[ks][0], WF1[ks][1]);
                MMAH(C, A1, WF0[ks][0], WF0[ks][1]);
            }
            const int r = lane >> 2, cc = 8 * w + 2 * (lane & 3);
            ghs[r][cc]         = C[0];
            ghs[r][cc + 1]     = C[1];
            ghs[r + 8][cc]     = C[2];
            ghs[r + 8][cc + 1] = C[3];
        }
        __syncthreads();

        // ---- gates for (ob, oj) ----
        float hr  = ghs[obb][ojl];
        float hz  = ghs[obb][16 + ojl];
        float hn3 = ghs[obb][32 + ojl];
        float hprev = __half2float(hs0[obb][oj]) + __half2float(hs1[obb][oj]);
        float r_ = 1.f / (1.f + expf(-(ir + hr + br)));
        float z_ = 1.f / (1.f + expf(-(iz + hz + bz)));
        float n_ = tanhf(inn + r_ * (hn3 + bn));
        g_h[(t + 1) & 1][ob * RNN_ + oj] = (1.f - z_) * n_ + z_ * hprev;

        // prefetch gi for t+1 before the barrier
        if (t + 1 < W_) {
            const float* gin = g_gi + ((size_t)(t + 1) * B_ + ob) * NGI;
            ir  = __ldcg(&gin[oj]);
            iz  = __ldcg(&gin[RNN_ + oj]);
            inn = __ldcg(&gin[2 * RNN_ + oj]);
        }

        // ---- per-bt flag barrier: arrive (own word) + spin on 16 words ----
        __threadfence();      // release: h stores visible before flag
        __syncthreads();      // all threads' h stores done before tid0 flags
        const unsigned tgt = fbase + (unsigned)(t + 1);
        if (tid == 0)
            *(volatile unsigned*)&g_flags[bt][jt] = tgt;
        if (tid < 16) {
            while (*(volatile unsigned*)&g_flags[bt][tid] < tgt) { }
        }
        __syncthreads();      // all 16 flags observed by lanes 0..15
        __threadfence();      // acquire: order h reads after flag observation
    }

    // ---- output head: 8 CTAs (jt==0), 16 b-rows x 10 outputs each ----
    if (jt == 0) {
        const float* hf = g_h[W_ & 1];   // final h after 31 steps
        for (int i = tid; i < 16 * OUT_; i += 256) {
            int bb = b0 + i / OUT_, o = i % OUT_;
            float s = 0.f;
            #pragma unroll 8
            for (int k = 0; k < RNN_; k += 4) {
                float4 h4 = __ldcg((const float4*)&hf[bb * RNN_ + k]);
                float4 w4 = *(const float4*)&Wout[o * RNN_ + k];
                s += h4.x * w4.x + h4.y * w4.y + h4.z * w4.z + h4.w * w4.w;
            }
            out[bb * OUT_ + o] = 1.f / (1.f + expf(-(s + bout[o])));
        }
    }
}

// =====================================================================
extern "C" void kernel_launch(void* const* d_in, const int* in_sizes, int n_in,
                              void* d_out, int out_size)
{
    const float* x     = (const float*)d_in[0];
    const float* W_aug = (const float*)d_in[1];
    // d_in[2] = b_aug: constant, cancels in increments
    const float* W_ih  = (const float*)d_in[3];
    const float* W_hh  = (const float*)d_in[4];
    const float* b_ih  = (const float*)d_in[5];
    const float* b_hh  = (const float*)d_in[6];
    const float* W_out = (const float*)d_in[7];
    const float* b_out = (const float*)d_in[8];
    float* out = (float*)d_out;

    cudaFuncSetAttribute(gemm_mma, cudaFuncAttributeMaxDynamicSharedMemorySize, GEMM_SMEM);

    sig_kernel<<<dim3(W_, B_ * G_), 128>>>(x, W_aug);
    prep_w<<<(NGI * KP2 + 255) / 256, 256>>>(W_ih);
    gemm_mma<<<dim3(MROWS / 64, NGI / 128), 256, GEMM_SMEM>>>(b_ih);
    gru_persist<<<GRU_CTAS, 256>>>(W_hh, b_hh, W_out, b_out, out);
}

// round 15
// speedup vs baseline: 1.4313x; 1.4313x over previous
#include <cuda_runtime.h>
#include <cuda_fp16.h>
#include <math.h>
#include <stdint.h>

// ---------------- problem constants ----------------
#define B_      128
#define STREAM_ 512
#define INCH    4
#define EXTRA_  5
#define G_      2
#define STEP_   16
#define SIGC    1110        // C + C^2 + C^3, C=10
#define W_      31          // windows
#define F_      2220        // GROUPS * SIGC
#define RNN_    256
#define OUT_    10
#define KP2     2240        // F_ padded to multiple of 64 (fp16 chunk)
#define MROWS   (W_ * B_)   // 3968
#define NGI     768         // 3 * RNN
#define NC      (KP2 / 64)  // 35 K-chunks of 64 fp16 (128 bytes)

// ---------------- device scratch (static, allowed) ----------------
__device__ __half g_A0[MROWS * KP2];          // sig fp16 (~17.8 MB)
__device__ __half g_B0[NGI * KP2];            // W_ih fp16 (~3.4 MB)
__device__ float g_gi[MROWS * NGI];           // [t][b][gate] (~12 MB)
__device__ float g_h [2][B_ * RNN_];          // ping-pong hidden state

// tree barrier: per-bt counters on separate 128B lines + global gen
__device__ unsigned g_cnt_bt[8][32];          // [bt][0] used
__device__ unsigned g_bar_cnt;
__device__ volatile unsigned g_bar_gen;

// ---------------- PTX helpers (portable: sm_80/90 class only) ----------------
__device__ __forceinline__ uint32_t smem_u32(const void* p) {
    uint32_t a;
    asm("{ .reg .u64 t; cvta.to.shared.u64 t, %1; cvt.u32.u64 %0, t; }" : "=r"(a) : "l"(p));
    return a;
}

__device__ __forceinline__ uint32_t swz(uint32_t off) { return off ^ ((off >> 3) & 0x70); }

#define LDSM4(r0, r1, r2, r3, addr)                                               \
    asm volatile("ldmatrix.sync.aligned.m8n8.x4.shared.b16 {%0,%1,%2,%3}, [%4];"  \
        : "=r"(r0), "=r"(r1), "=r"(r2), "=r"(r3) : "r"(addr))

// D += A(16x16) * B(16x8), fp16 in, fp32 accum. row.col = both K-contiguous.
#define MMAH(d, a, b0v, b1v)                                                      \
    asm volatile("mma.sync.aligned.m16n8k16.row.col.f32.f16.f16.f32 "             \
        "{%0,%1,%2,%3}, {%4,%5,%6,%7}, {%8,%9}, {%0,%1,%2,%3};"                   \
        : "+f"((d)[0]), "+f"((d)[1]), "+f"((d)[2]), "+f"((d)[3])                  \
        : "r"((a)[0]), "r"((a)[1]), "r"((a)[2]), "r"((a)[3]), "r"(b0v), "r"(b1v))

__device__ __forceinline__ uint32_t pack_h2(float a, float b) {
    __half2 h = __halves2half2(__float2half_rn(a), __float2half_rn(b));
    return *(uint32_t*)&h;
}

// =====================================================================
// Kernel 1: path signatures (Chen, depth 3) -> fp16 (single-rounded)
// =====================================================================
__global__ __launch_bounds__(128) void sig_kernel(
    const float* __restrict__ x,       // (128,512,4)
    const float* __restrict__ W_aug)   // (2,5,4)
{
    const int w  = blockIdx.x;
    const int bg = blockIdx.y;
    const int b  = bg >> 1;
    const int g  = bg & 1;
    const int tid = threadIdx.x;

    __shared__ __align__(16) float xs[32][4];
    __shared__ __align__(16) float dxw[31][10];

    {
        int row = tid >> 2, ch = tid & 3;
        xs[row][ch] = x[(b * STREAM_ + w * STEP_ + row) * INCH + ch];
    }
    __syncthreads();

    for (int idx = tid; idx < 31 * 10; idx += 128) {
        int j = idx / 10, c = idx % 10;
        float v;
        if (c < 4) {
            v = xs[j + 1][c] - xs[j][c];
        } else if (c == 4) {
            v = 1.0f / 511.0f;
        } else {
            int e = c - 5;
            const float* wa = W_aug + (g * EXTRA_ + e) * INCH;
            v = 0.f;
            #pragma unroll
            for (int i = 0; i < 4; i++) v += wa[i] * (xs[j + 1][i] - xs[j][i]);
        }
        dxw[j][c] = v;
    }
    __syncthreads();

    const size_t base = (size_t)(w * B_ + b) * KP2 + (size_t)g * SIGC;

    if (tid < 100) {
        const int a  = tid / 10;
        const int bb = tid % 10;
        float s1a = 0.f, s2 = 0.f;
        float s3[10];
        #pragma unroll
        for (int c = 0; c < 10; c++) s3[c] = 0.f;

        for (int j = 0; j < 31; j++) {
            float dxa = dxw[j][a];
            float dxb = dxw[j][bb];
            float factor = s2 + dxb * (0.5f * s1a + (1.0f / 6.0f) * dxa);
            #pragma unroll
            for (int c = 0; c < 10; c++) s3[c] += factor * dxw[j][c];
            s2  += dxb * (s1a + 0.5f * dxa);
            s1a += dxa;
        }
        if (bb == 0) g_A0[base + a] = __float2half_rn(s1a);
        g_A0[base + 10 + tid] = __float2half_rn(s2);
        #pragma unroll
        for (int c = 0; c < 10; c++)
            g_A0[base + 110 + tid * 10 + c] = __float2half_rn(s3[c]);
    }
    // zero K-pad columns (g==1 block handles it once per row)
    if (g == 1 && tid < (KP2 - F_))
        g_A0[(size_t)(w * B_ + b) * KP2 + F_ + tid] = __float2half_rn(0.f);
}

// =====================================================================
// Kernel 2: round+pad W_ih (768 x 2220) into g_B0 (768 x 2240) fp16
// =====================================================================
__global__ __launch_bounds__(256) void prep_w(const float* __restrict__ Wih)
{
    int idx = blockIdx.x * 256 + threadIdx.x;
    if (idx < NGI * KP2) {
        int n = idx / KP2, k = idx - n * KP2;
        float v = (k < F_) ? Wih[n * F_ + k] : 0.f;
        g_B0[idx] = __float2half_rn(v);
    }
}

// =====================================================================
// Kernel 3: GI = sig @ W_ih^T + b_ih, SINGLE-product fp16 mma.sync.
// 64x128 CTA tile (372 CTAs, 2/SM), 8 warps of 32(M)x32(N).
// =====================================================================
#define A_TILE_B    8192                   // 64 rows x 128 bytes
#define B_TILE_B    16384                  // 128 rows x 128 bytes
#define STAGE_B     (A_TILE_B + B_TILE_B)  // 24576
#define GEMM_SMEM   (2 * STAGE_B)          // 49152 bytes (2 stages)

__global__ __launch_bounds__(256, 2) void gemm_mma(const float* __restrict__ bih)
{
    extern __shared__ char smem[];
    const uint32_t sb = smem_u32(smem);
    const int tid  = threadIdx.x;
    const int lane = tid & 31;
    const int wid  = tid >> 5;
    const int wm   = wid & 1;         // M offset 32*wm
    const int wn   = wid >> 1;        // 0..3 -> N offset 32*wn
    const int m0 = blockIdx.x * 64;
    const int n0 = blockIdx.y * 128;

    const __half* aA0  = g_A0 + (size_t)m0 * KP2;
    const __half* bB0g = g_B0 + (size_t)n0 * KP2;

    auto load_chunk = [&](int c) {
        uint32_t sbase = sb + (uint32_t)(c & 1) * STAGE_B;
        #pragma unroll
        for (int it = 0; it < 2; it++) {
            int i = tid + it * 256;               // 0..511
            int row = i >> 3, seg = i & 7;
            uint32_t dst = sbase + swz((uint32_t)row * 128 + (uint32_t)seg * 16);
            const void* src = aA0 + (size_t)row * KP2 + (size_t)c * 64 + seg * 8;
            asm volatile("cp.async.cg.shared.global [%0], [%1], 16;\n"
                         :: "r"(dst), "l"(src));
        }
        #pragma unroll
        for (int it = 0; it < 4; it++) {
            int i = tid + it * 256;               // 0..1023
            int row = i >> 3, seg = i & 7;
            uint32_t dst = sbase + A_TILE_B
                         + swz((uint32_t)row * 128 + (uint32_t)seg * 16);
            const void* src = bB0g + (size_t)row * KP2 + (size_t)c * 64 + seg * 8;
            asm volatile("cp.async.cg.shared.global [%0], [%1], 16;\n"
                         :: "r"(dst), "l"(src));
        }
        asm volatile("cp.async.commit_group;\n" ::: "memory");
    };

    float acc[2][4][4];
    #pragma unroll
    for (int i = 0; i < 2; i++)
        #pragma unroll
        for (int jj = 0; jj < 4; jj++)
            #pragma unroll
            for (int k = 0; k < 4; k++) acc[i][jj][k] = 0.f;

    const uint32_t a_row  = (uint32_t)(wm * 32 + (lane & 15));
    const uint32_t a_byte = (uint32_t)((lane >> 4) << 4);
    const uint32_t b_row  = (uint32_t)(wn * 32 + (lane & 7) + ((lane >> 4) << 3));
    const uint32_t b_byte = (uint32_t)((lane & 8) << 1);

    load_chunk(0);

    for (int c = 0; c < NC; c++) {
        if (c + 1 < NC) load_chunk(c + 1);
        if (c + 1 < NC) asm volatile("cp.async.wait_group 1;\n" ::: "memory");
        else            asm volatile("cp.async.wait_group 0;\n" ::: "memory");
        __syncthreads();

        const uint32_t stage = sb + (uint32_t)(c & 1) * STAGE_B;
        const uint32_t aB0 = stage;
        const uint32_t bB0 = stage + A_TILE_B;

        #pragma unroll
        for (int ks = 0; ks < 4; ks++) {
            const uint32_t kb = (uint32_t)ks * 32;
            uint32_t a0f[2][4];
            #pragma unroll
            for (int mt = 0; mt < 2; mt++) {
                uint32_t off = swz((a_row + mt * 16) * 128 + kb + a_byte);
                LDSM4(a0f[mt][0], a0f[mt][1], a0f[mt][2], a0f[mt][3], aB0 + off);
            }
            uint32_t b0f[2][4];
            #pragma unroll
            for (int nt = 0; nt < 2; nt++) {
                uint32_t off = swz((b_row + nt * 16) * 128 + kb + b_byte);
                LDSM4(b0f[nt][0], b0f[nt][1], b0f[nt][2], b0f[nt][3], bB0 + off);
            }
            #pragma unroll
            for (int mt = 0; mt < 2; mt++) {
                #pragma unroll
                for (int nt = 0; nt < 2; nt++) {
                    MMAH(acc[mt][2 * nt],     a0f[mt], b0f[nt][0], b0f[nt][1]);
                    MMAH(acc[mt][2 * nt + 1], a0f[mt], b0f[nt][2], b0f[nt][3]);
                }
            }
        }
        __syncthreads();
    }

    float2 bias[4];
    {
        const int nbase = n0 + wn * 32 + 2 * (lane & 3);
        #pragma unroll
        for (int nt8 = 0; nt8 < 4; nt8++) {
            bias[nt8].x = bih[nbase + nt8 * 8];
            bias[nt8].y = bih[nbase + nt8 * 8 + 1];
        }
    }
    #pragma unroll
    for (int mt = 0; mt < 2; mt++) {
        const int mlo = m0 + wm * 32 + mt * 16 + (lane >> 2);
        #pragma unroll
        for (int nt8 = 0; nt8 < 4; nt8++) {
            const int n = n0 + wn * 32 + nt8 * 8 + 2 * (lane & 3);
            float2 lo, hi;
            lo.x = acc[mt][nt8][0] + bias[nt8].x;
            lo.y = acc[mt][nt8][1] + bias[nt8].y;
            hi.x = acc[mt][nt8][2] + bias[nt8].x;
            hi.y = acc[mt][nt8][3] + bias[nt8].y;
            *(float2*)(g_gi + (size_t)mlo * NGI + n)       = lo;
            *(float2*)(g_gi + (size_t)(mlo + 8) * NGI + n) = hi;
        }
    }
}

// =====================================================================
// Kernel 4: persistent GRU v6 — MMA gh (R13) + TREE-arrival global
// barrier (per-bt atomic level 1, 8-way global level 2, single gen
// release + nanosleep spin exactly as R13). 128 CTAs = 8 bt x 16 jt.
// =====================================================================
#define GRU_CTAS   128
#define HROWH      264      // 256 + 8 halves pad (conflict-free LDSM)

__global__ __launch_bounds__(256, 1) void gru_persist(
    const float* __restrict__ Whh,   // (768,256)
    const float* __restrict__ bhh,   // (768)
    const float* __restrict__ Wout,  // (10,256)
    const float* __restrict__ bout,  // (10)
    float* __restrict__ out)         // (128,10)
{
    __shared__ __align__(16) __half hs0[16][HROWH];   // 8.25 KB
    __shared__ __align__(16) __half hs1[16][HROWH];
    __shared__ __align__(16) float  ghs[16][66];      // 4.1 KB

    const int tid  = threadIdx.x;
    const int w    = tid >> 5;
    const int lane = tid & 31;
    const int bt = blockIdx.x >> 4, jt = blockIdx.x & 15;
    const int b0 = bt * 16, j0 = jt * 16;

    // this thread's gate-output assignment (independent of warp role)
    const int obb = tid >> 4, ojl = tid & 15;
    const int ob  = b0 + obb, oj = j0 + ojl;
    const float br = bhh[oj], bz = bhh[RNN_ + oj], bn = bhh[2 * RNN_ + oj];

    // ---- one-time: W_hh B-fragments (W0 + residual W1) in registers ----
    const bool active = (w < 6);
    uint32_t WF0[16][2], WF1[16][2];
    if (active) {
        const int colg = 8 * w + (lane >> 2);            // 0..47
        const int jrow = (colg >> 4) * RNN_ + j0 + (colg & 15);
        const float* wr = Whh + (size_t)jrow * RNN_;
        const int k2 = (lane & 3) * 2;
        #pragma unroll
        for (int ks = 0; ks < 16; ks++) {
            const int kb = ks * 16 + k2;
            float v0 = wr[kb], v1 = wr[kb + 1], v8 = wr[kb + 8], v9 = wr[kb + 9];
            __half h0 = __float2half_rn(v0), h1 = __float2half_rn(v1);
            __half h8 = __float2half_rn(v8), h9 = __float2half_rn(v9);
            WF0[ks][0] = pack_h2(v0, v1);
            WF0[ks][1] = pack_h2(v8, v9);
            WF1[ks][0] = pack_h2(v0 - __half2float(h0), v1 - __half2float(h1));
            WF1[ks][1] = pack_h2(v8 - __half2float(h8), v9 - __half2float(h9));
        }
    }

    // prefetch gi for t=0
    float ir, iz, inn;
    {
        const float* gi0 = g_gi + (size_t)ob * NGI;
        ir  = __ldcg(&gi0[oj]);
        iz  = __ldcg(&gi0[RNN_ + oj]);
        inn = __ldcg(&gi0[2 * RNN_ + oj]);
    }

    const uint32_t hb0 = smem_u32(&hs0[0][0]);
    const uint32_t hb1 = smem_u32(&hs1[0][0]);
    const uint32_t aoff_base = (uint32_t)(lane & 15) * (HROWH * 2)
                             + (uint32_t)((lane >> 4) << 4);

    for (int t = 0; t < W_; t++) {
        // ---- fill hs0/hs1 with exact fp16 split of h_t (zeros at t=0) ----
        if (t == 0) {
            for (int i = tid; i < 16 * HROWH / 2; i += 256) {
                ((uint32_t*)hs0)[i] = 0u;
                ((uint32_t*)hs1)[i] = 0u;
            }
        } else {
            const float* hi = g_h[t & 1];
            const int row = tid >> 4, cb = (tid & 15) * 16;
            const float* src = &hi[(b0 + row) * RNN_ + cb];
            float v[16];
            #pragma unroll
            for (int q = 0; q < 4; q++)
                *(float4*)&v[q * 4] = __ldcg((const float4*)&src[q * 4]);
            uint32_t p0[8], p1[8];
            #pragma unroll
            for (int e = 0; e < 8; e++) {
                float a = v[2 * e], bvl = v[2 * e + 1];
                __half ha = __float2half_rn(a), hbv = __float2half_rn(bvl);
                p0[e] = pack_h2(a, bvl);
                p1[e] = pack_h2(a - __half2float(ha), bvl - __half2float(hbv));
            }
            uint32_t* d0 = (uint32_t*)&hs0[row][cb];
            uint32_t* d1 = (uint32_t*)&hs1[row][cb];
            *(uint4*)&d0[0] = *(uint4*)&p0[0];
            *(uint4*)&d0[4] = *(uint4*)&p0[4];
            *(uint4*)&d1[0] = *(uint4*)&p1[0];
            *(uint4*)&d1[4] = *(uint4*)&p1[4];
        }
        __syncthreads();

        // ---- MMA: gh[16][8] per active warp, K=256 ----
        if (active) {
            float C[4] = {0.f, 0.f, 0.f, 0.f};
            #pragma unroll
            for (int ks = 0; ks < 16; ks++) {
                const uint32_t off = aoff_base + (uint32_t)ks * 32;
                uint32_t A0[4], A1[4];
                LDSM4(A0[0], A0[1], A0[2], A0[3], hb0 + off);
                LDSM4(A1[0], A1[1], A1[2], A1[3], hb1 + off);
                MMAH(C, A0, WF0[ks][0], WF0[ks][1]);
                MMAH(C, A0, WF1[ks][0], WF1[ks][1]);
                MMAH(C, A1, WF0[ks][0], WF0[ks][1]);
            }
            const int r = lane >> 2, cc = 8 * w + 2 * (lane & 3);
            ghs[r][cc]         = C[0];
            ghs[r][cc + 1]     = C[1];
            ghs[r + 8][cc]     = C[2];
            ghs[r + 8][cc + 1] = C[3];
        }
        __syncthreads();

        // ---- gates for (ob, oj) ----
        float hr  = ghs[obb][ojl];
        float hz  = ghs[obb][16 + ojl];
        float hn3 = ghs[obb][32 + ojl];
        float hprev = __half2float(hs0[obb][oj]) + __half2float(hs1[obb][oj]);
        float r_ = 1.f / (1.f + expf(-(ir + hr + br)));
        float z_ = 1.f / (1.f + expf(-(iz + hz + bz)));
        float n_ = tanhf(inn + r_ * (hn3 + bn));
        g_h[(t + 1) & 1][ob * RNN_ + oj] = (1.f - z_) * n_ + z_ * hprev;

        // prefetch gi for t+1 before the barrier
        if (t + 1 < W_) {
            const float* gin = g_gi + ((size_t)(t + 1) * B_ + ob) * NGI;
            ir  = __ldcg(&gin[oj]);
            iz  = __ldcg(&gin[RNN_ + oj]);
            inn = __ldcg(&gin[2 * RNN_ + oj]);
        }

        // ---- global barrier, TREE arrival (16-way bt level + 8-way root),
        //      single gen release + nanosleep spin (proven R13 pattern) ----
        __threadfence();
        __syncthreads();
        if (tid == 0) {
            unsigned gen = g_bar_gen;
            if (atomicAdd(&g_cnt_bt[bt][0], 1u) == 15u) {
                g_cnt_bt[bt][0] = 0;                     // safe: pre-release
                if (atomicAdd(&g_bar_cnt, 1u) == 7u) {
                    g_bar_cnt = 0;
                    __threadfence();
                    g_bar_gen = gen + 1;
                }
            }
            while (g_bar_gen == gen) __nanosleep(32);
        }
        __syncthreads();
    }

    // ---- output head: 8 CTAs (jt==0), 16 b-rows x 10 outputs each ----
    if (jt == 0) {
        const float* hf = g_h[W_ & 1];   // final h after 31 steps
        for (int i = tid; i < 16 * OUT_; i += 256) {
            int bb = b0 + i / OUT_, o = i % OUT_;
            float s = 0.f;
            #pragma unroll 8
            for (int k = 0; k < RNN_; k += 4) {
                float4 h4 = __ldcg((const float4*)&hf[bb * RNN_ + k]);
                float4 w4 = *(const float4*)&Wout[o * RNN_ + k];
                s += h4.x * w4.x + h4.y * w4.y + h4.z * w4.z + h4.w * w4.w;
            }
            out[bb * OUT_ + o] = 1.f / (1.f + expf(-(s + bout[o])));
        }
    }
}

// =====================================================================
extern "C" void kernel_launch(void* const* d_in, const int* in_sizes, int n_in,
                              void* d_out, int out_size)
{
    const float* x     = (const float*)d_in[0];
    const float* W_aug = (const float*)d_in[1];
    // d_in[2] = b_aug: constant, cancels in increments
    const float* W_ih  = (const float*)d_in[3];
    const float* W_hh  = (const float*)d_in[4];
    const float* b_ih  = (const float*)d_in[5];
    const float* b_hh  = (const float*)d_in[6];
    const float* W_out = (const float*)d_in[7];
    const float* b_out = (const float*)d_in[8];
    float* out = (float*)d_out;

    cudaFuncSetAttribute(gemm_mma, cudaFuncAttributeMaxDynamicSharedMemorySize, GEMM_SMEM);

    sig_kernel<<<dim3(W_, B_ * G_), 128>>>(x, W_aug);
    prep_w<<<(NGI * KP2 + 255) / 256, 256>>>(W_ih);
    gemm_mma<<<dim3(MROWS / 64, NGI / 128), 256, GEMM_SMEM>>>(b_ih);
    gru_persist<<<GRU_CTAS, 256>>>(W_hh, b_hh, W_out, b_out, out);
}